// round 15
// baseline (speedup 1.0000x reference)
#include <cuda_runtime.h>
#include <cuda_bf16.h>
#include <math.h>

#define B_   4
#define HW_  4096          // 64*64
#define C_   512
#define G_   32
#define CG_  16
#define MTOT (B_*HW_)      // 16384

typedef __nv_bfloat16 bf16;

// ---------------- scratch (device globals; no allocations allowed) ----------
__device__ bf16          g_xn[(size_t)MTOT*C_];
__device__ unsigned char g_qk8[(size_t)MTOT*2*C_];     // fp8 Q|K [16384][1024]
__device__ unsigned char g_vt8[(size_t)B_*C_*HW_];     // fp8 V^T [512][4096]/batch
__device__ unsigned char g_p8 [(size_t)B_*HW_*HW_];    // fp8 exp-scores 64 MiB
__device__ bf16          g_ao[(size_t)MTOT*C_];
__device__ bf16          g_wT[(size_t)4*C_*C_];        // q,k,v,o transposed bf16
__device__ float         g_rowsum[(size_t)MTOT];       // softmax denominators
__device__ float         g_bqk[2*C_];                  // bq || bk

// ======================= helpers =============================================
__device__ __forceinline__ unsigned smem_u32(const void* p) {
    unsigned a;
    asm("{ .reg .u64 t; cvta.to.shared.u64 t, %1; cvt.u32.u64 %0, t; }"
        : "=r"(a) : "l"(p));
    return a;
}
__device__ __forceinline__ unsigned pack2(float a, float b) {
    __nv_bfloat162 t = __floats2bfloat162_rn(a, b);
    return *reinterpret_cast<unsigned*>(&t);
}
// pack two f32 into e4m3x2: low byte = lo, high byte = hi
__device__ __forceinline__ unsigned short pack_e4m3x2(float lo, float hi) {
    unsigned short r;
    asm("cvt.rn.satfinite.e4m3x2.f32 %0, %1, %2;" : "=h"(r) : "f"(hi), "f"(lo));
    return r;
}

#define LDMX4(r, addr) \
    asm volatile("ldmatrix.sync.aligned.m8n8.x4.shared.b16 {%0,%1,%2,%3}, [%4];" \
        : "=r"((r)[0]), "=r"((r)[1]), "=r"((r)[2]), "=r"((r)[3]) : "r"(addr))

#define MMA16816(c, a, b0, b1) \
    asm volatile("mma.sync.aligned.m16n8k16.row.col.f32.bf16.bf16.f32 " \
        "{%0,%1,%2,%3}, {%4,%5,%6,%7}, {%8,%9}, {%0,%1,%2,%3};" \
        : "+f"((c)[0]), "+f"((c)[1]), "+f"((c)[2]), "+f"((c)[3]) \
        : "r"((a)[0]), "r"((a)[1]), "r"((a)[2]), "r"((a)[3]), "r"(b0), "r"(b1))

#define MMAFP8(c, a, b0, b1) \
    asm volatile("mma.sync.aligned.m16n8k32.row.col.f32.e4m3.e4m3.f32 " \
        "{%0,%1,%2,%3}, {%4,%5,%6,%7}, {%8,%9}, {%0,%1,%2,%3};" \
        : "+f"((c)[0]), "+f"((c)[1]), "+f"((c)[2]), "+f"((c)[3]) \
        : "r"((a)[0]), "r"((a)[1]), "r"((a)[2]), "r"((a)[3]), "r"(b0), "r"(b1))

// ---------------- GroupNorm -> bf16 ----------------------------------------
__global__ __launch_bounds__(256) void groupnorm_kernel(
    const float* __restrict__ x, const float* __restrict__ gamma,
    const float* __restrict__ beta, bf16* __restrict__ xn)
{
    int bg = blockIdx.x;
    int b = bg / G_, g = bg % G_;
    const float* xp = x + (size_t)b * HW_ * C_ + g * CG_;
    bf16* op = xn + (size_t)b * HW_ * C_ + g * CG_;
    int tid = threadIdx.x;

    float s = 0.f, ss = 0.f;
    for (int p = tid; p < HW_; p += 256) {
        const float4* v4 = (const float4*)(xp + (size_t)p * C_);
        #pragma unroll
        for (int i = 0; i < 4; i++) {
            float4 t = v4[i];
            s  += t.x + t.y + t.z + t.w;
            ss += t.x*t.x + t.y*t.y + t.z*t.z + t.w*t.w;
        }
    }
    __shared__ float rs[256], rq[256];
    rs[tid] = s; rq[tid] = ss; __syncthreads();
    for (int o = 128; o > 0; o >>= 1) {
        if (tid < o) { rs[tid] += rs[tid+o]; rq[tid] += rq[tid+o]; }
        __syncthreads();
    }
    const float invn = 1.0f / (HW_ * CG_);
    float mean = rs[0] * invn;
    float var  = rq[0] * invn - mean * mean;
    float rstd = rsqrtf(var + 1e-6f);

    float gm[CG_], bt[CG_];
    #pragma unroll
    for (int i = 0; i < CG_; i++) {
        gm[i] = gamma[g*CG_ + i];
        bt[i] = beta [g*CG_ + i];
    }

    for (int p = tid; p < HW_; p += 256) {
        const float4* v4 = (const float4*)(xp + (size_t)p * C_);
        uint2* o2 = (uint2*)(op + (size_t)p * C_);
        #pragma unroll
        for (int i = 0; i < 4; i++) {
            float4 t = v4[i];
            float a0 = (t.x - mean) * rstd * gm[i*4+0] + bt[i*4+0];
            float a1 = (t.y - mean) * rstd * gm[i*4+1] + bt[i*4+1];
            float a2 = (t.z - mean) * rstd * gm[i*4+2] + bt[i*4+2];
            float a3 = (t.w - mean) * rstd * gm[i*4+3] + bt[i*4+3];
            uint2 u; u.x = pack2(a0, a1); u.y = pack2(a2, a3);
            o2[i] = u;
        }
    }
}

// ---------------- weight transpose+convert ----------------------------------
__global__ __launch_bounds__(256) void wtrans_kernel(
    const float* __restrict__ w0, const float* __restrict__ w1,
    const float* __restrict__ w2, const float* __restrict__ w3,
    bf16* __restrict__ out)
{
    int z = blockIdx.z;
    const float* w = (z == 0) ? w0 : (z == 1) ? w1 : (z == 2) ? w2 : w3;
    bf16* o = out + (size_t)z * C_ * C_;
    __shared__ float t[32][33];
    int c0 = blockIdx.x * 32, d0 = blockIdx.y * 32;
    int tx = threadIdx.x & 31, ty = threadIdx.x >> 5;
    #pragma unroll
    for (int i = 0; i < 32; i += 8)
        t[ty+i][tx] = w[(size_t)(c0+ty+i) * C_ + d0 + tx];
    __syncthreads();
    #pragma unroll
    for (int i = 0; i < 32; i += 8)
        o[(size_t)(d0+ty+i) * C_ + c0 + tx] = __float2bfloat16(t[tx][ty+i]);
}

// ---------------- tiny setup kernel -----------------------------------------
__global__ void setup_kernel(const float* __restrict__ bq,
                             const float* __restrict__ bk,
                             float* __restrict__ bqk,
                             float* __restrict__ rowsum)
{
    int i = blockIdx.x * 256 + threadIdx.x;
    if (i < 2*C_) bqk[i] = (i < C_) ? bq[i] : bk[i - C_];
    if (i < MTOT) rowsum[i] = 0.f;
}

// ---------------- bf16 HMMA GEMM (projections / out-proj) -------------------
// Block tile 128x128x64, 8 warps (2x4), warp tile 64x32, 2-stage cp.async.
#define KT 64
#define STAGE_BYTES 32768   // A 16KB + B 16KB

__device__ __forceinline__ void load_stage(
    unsigned base, const bf16* __restrict__ A, const bf16* __restrict__ B,
    int lda, int ldb, int brow, int bcol, int k0, int tid)
{
    #pragma unroll
    for (int i = 0; i < 4; i++) {
        int id  = i * 256 + tid;
        int row = id >> 3, cg = id & 7;
        const bf16* ga = A + (long long)(brow + row) * lda + k0 + cg * 8;
        unsigned sa = base + row * 128 + ((cg ^ (row & 7)) << 4);
        asm volatile("cp.async.cg.shared.global [%0], [%1], 16;" :: "r"(sa), "l"(ga));
        const bf16* gb = B + (long long)(bcol + row) * ldb + k0 + cg * 8;
        unsigned sb = base + 16384 + row * 128 + ((cg ^ (row & 7)) << 4);
        asm volatile("cp.async.cg.shared.global [%0], [%1], 16;" :: "r"(sb), "l"(gb));
    }
}

__global__ void __launch_bounds__(256, 2) gemm_bf16(
    const bf16* __restrict__ A, const bf16* __restrict__ B,
    int M, int N, int K, int lda, int ldb, int ldc,
    long long sA, long long sB, long long sC,
    float alpha,
    const float* __restrict__ cbias,
    const float* __restrict__ rbias,
    const float* __restrict__ resid,
    float* __restrict__ Cf, bf16* __restrict__ Cb,
    unsigned char* __restrict__ C8)
{
    extern __shared__ char smem[];
    const unsigned s0 = smem_u32(smem);
    const int tid = threadIdx.x, wid = tid >> 5, lane = tid & 31;
    const int warp_m = wid & 1, warp_n = wid >> 1;

    A += (long long)blockIdx.z * sA;
    B += (long long)blockIdx.z * sB;
    const long long cb0 = (long long)blockIdx.z * sC;
    const int brow = blockIdx.y * 128, bcol = blockIdx.x * 128;

    const int g  = lane >> 3, li = lane & 7;
    const int rowA = (g & 1) * 8 + li;
    const int kselA = g >> 1;
    const int rowB = (g >> 1) * 8 + li;
    const int kselB = g & 1;

    float acc[4][4][4];
    #pragma unroll
    for (int mt = 0; mt < 4; mt++)
        #pragma unroll
        for (int nt = 0; nt < 4; nt++)
            #pragma unroll
            for (int e = 0; e < 4; e++) acc[mt][nt][e] = 0.f;

    const int nc = K / KT;

    load_stage(s0, A, B, lda, ldb, brow, bcol, 0, tid);
    asm volatile("cp.async.commit_group;");

    for (int t = 0; t < nc; t++) {
        if (t + 1 < nc) {
            load_stage(s0 + ((t + 1) & 1) * STAGE_BYTES, A, B, lda, ldb,
                       brow, bcol, (t + 1) * KT, tid);
            asm volatile("cp.async.commit_group;");
            asm volatile("cp.async.wait_group 1;");
        } else {
            asm volatile("cp.async.wait_group 0;");
        }
        __syncthreads();

        const unsigned aBase = s0 + (t & 1) * STAGE_BYTES;
        const unsigned bBase = aBase + 16384;
        #pragma unroll
        for (int kk = 0; kk < 4; kk++) {
            unsigned af[4][4];
            #pragma unroll
            for (int mt = 0; mt < 4; mt++) {
                int r = warp_m * 64 + mt * 16 + rowA;
                unsigned addr = aBase + r * 128 + (((kk * 2 + kselA) ^ li) << 4);
                LDMX4(af[mt], addr);
            }
            unsigned bfx[2][4];
            #pragma unroll
            for (int nh = 0; nh < 2; nh++) {
                int r = warp_n * 32 + nh * 16 + rowB;
                unsigned addr = bBase + r * 128 + (((kk * 2 + kselB) ^ li) << 4);
                LDMX4(bfx[nh], addr);
            }
            #pragma unroll
            for (int mt = 0; mt < 4; mt++) {
                #pragma unroll
                for (int nt = 0; nt < 4; nt++) {
                    unsigned b0 = bfx[nt >> 1][(nt & 1) * 2];
                    unsigned b1 = bfx[nt >> 1][(nt & 1) * 2 + 1];
                    MMA16816(acc[mt][nt], af[mt], b0, b1);
                }
            }
        }
        __syncthreads();
    }

    const int er = lane >> 2, ec = (lane & 3) * 2;
    #pragma unroll
    for (int mt = 0; mt < 4; mt++) {
        #pragma unroll
        for (int half = 0; half < 2; half++) {
            long long grow = brow + warp_m * 64 + mt * 16 + er + half * 8;
            float rb = rbias ? rbias[grow] : 0.f;
            #pragma unroll
            for (int nt = 0; nt < 4; nt++) {
                int col = bcol + warp_n * 32 + nt * 8 + ec;
                float v0 = acc[mt][nt][half * 2]     * alpha + rb;
                float v1 = acc[mt][nt][half * 2 + 1] * alpha + rb;
                if (cbias) { v0 += cbias[col]; v1 += cbias[col + 1]; }
                long long base = cb0 + grow * (long long)ldc + col;
                if (resid) {
                    float2 r = *(const float2*)(resid + base);
                    v0 += r.x; v1 += r.y;
                }
                if (C8) {
                    *(unsigned short*)(C8 + base) = pack_e4m3x2(v0, v1);
                } else if (Cf) {
                    float2 o = {v0, v1};
                    *(float2*)(Cf + base) = o;
                } else {
                    *(unsigned*)(Cb + base) = pack2(v0, v1);
                }
            }
        }
    }
}

// ---------------- fp8 HMMA GEMM (attention): C = alpha*A@B^T ----------------
// A: [M,K] e4m3 row-major. B: [N,K] e4m3 row-major. K-chunk = 128 fp8 = 128B
// rows; byte-identical smem layout / ldmatrix addressing as the bf16 kernel
// (fp8 pairs viewed as b16). mma m16n8k32.e4m3, fp32 accum.
#define KT8 128

__device__ __forceinline__ void load_stage8(
    unsigned base, const unsigned char* __restrict__ A,
    const unsigned char* __restrict__ B,
    int lda, int ldb, int brow, int bcol, int k0, int tid)
{
    #pragma unroll
    for (int i = 0; i < 4; i++) {
        int id  = i * 256 + tid;
        int row = id >> 3, cg = id & 7;
        const unsigned char* ga = A + (long long)(brow + row) * lda + k0 + cg * 16;
        unsigned sa = base + row * 128 + ((cg ^ (row & 7)) << 4);
        asm volatile("cp.async.cg.shared.global [%0], [%1], 16;" :: "r"(sa), "l"(ga));
        const unsigned char* gb = B + (long long)(bcol + row) * ldb + k0 + cg * 16;
        unsigned sb = base + 16384 + row * 128 + ((cg ^ (row & 7)) << 4);
        asm volatile("cp.async.cg.shared.global [%0], [%1], 16;" :: "r"(sb), "l"(gb));
    }
}

__global__ void __launch_bounds__(256, 2) gemm_fp8(
    const unsigned char* __restrict__ A, const unsigned char* __restrict__ B,
    int M, int N, int K, int lda, int ldb, int ldc,
    float alpha,
    unsigned char* __restrict__ C8, bf16* __restrict__ Cb,
    int do_exp, float* __restrict__ rowsum,
    const float* __restrict__ rdiv)
{
    extern __shared__ char smem[];
    const unsigned s0 = smem_u32(smem);
    const int tid = threadIdx.x, wid = tid >> 5, lane = tid & 31;
    const int warp_m = wid & 1, warp_n = wid >> 1;

    const int brow = blockIdx.y * 128, bcol = blockIdx.x * 128;

    const int g  = lane >> 3, li = lane & 7;
    const int rowA = (g & 1) * 8 + li;
    const int kselA = g >> 1;
    const int rowB = (g >> 1) * 8 + li;
    const int kselB = g & 1;

    float acc[4][4][4];
    #pragma unroll
    for (int mt = 0; mt < 4; mt++)
        #pragma unroll
        for (int nt = 0; nt < 4; nt++)
            #pragma unroll
            for (int e = 0; e < 4; e++) acc[mt][nt][e] = 0.f;

    const int nc = K / KT8;

    load_stage8(s0, A, B, lda, ldb, brow, bcol, 0, tid);
    asm volatile("cp.async.commit_group;");

    for (int t = 0; t < nc; t++) {
        if (t + 1 < nc) {
            load_stage8(s0 + ((t + 1) & 1) * STAGE_BYTES, A, B, lda, ldb,
                        brow, bcol, (t + 1) * KT8, tid);
            asm volatile("cp.async.commit_group;");
            asm volatile("cp.async.wait_group 1;");
        } else {
            asm volatile("cp.async.wait_group 0;");
        }
        __syncthreads();

        const unsigned aBase = s0 + (t & 1) * STAGE_BYTES;
        const unsigned bBase = aBase + 16384;
        #pragma unroll
        for (int kk = 0; kk < 4; kk++) {
            unsigned af[4][4];
            #pragma unroll
            for (int mt = 0; mt < 4; mt++) {
                int r = warp_m * 64 + mt * 16 + rowA;
                unsigned addr = aBase + r * 128 + (((kk * 2 + kselA) ^ li) << 4);
                LDMX4(af[mt], addr);
            }
            unsigned bfx[2][4];
            #pragma unroll
            for (int nh = 0; nh < 2; nh++) {
                int r = warp_n * 32 + nh * 16 + rowB;
                unsigned addr = bBase + r * 128 + (((kk * 2 + kselB) ^ li) << 4);
                LDMX4(bfx[nh], addr);
            }
            #pragma unroll
            for (int mt = 0; mt < 4; mt++) {
                #pragma unroll
                for (int nt = 0; nt < 4; nt++) {
                    unsigned b0 = bfx[nt >> 1][(nt & 1) * 2];
                    unsigned b1 = bfx[nt >> 1][(nt & 1) * 2 + 1];
                    MMAFP8(acc[mt][nt], af[mt], b0, b1);
                }
            }
        }
        __syncthreads();
    }

    const int er = lane >> 2, ec = (lane & 3) * 2;
    #pragma unroll
    for (int mt = 0; mt < 4; mt++) {
        #pragma unroll
        for (int half = 0; half < 2; half++) {
            long long grow = brow + warp_m * 64 + mt * 16 + er + half * 8;
            float rsc = rdiv ? (1.0f / rdiv[grow]) : 1.0f;
            float part = 0.f;
            #pragma unroll
            for (int nt = 0; nt < 4; nt++) {
                int col = bcol + warp_n * 32 + nt * 8 + ec;
                float v0 = acc[mt][nt][half * 2]     * alpha;
                float v1 = acc[mt][nt][half * 2 + 1] * alpha;
                if (do_exp) { v0 = __expf(v0); v1 = __expf(v1); part += v0 + v1; }
                v0 *= rsc; v1 *= rsc;
                long long base = grow * (long long)ldc + col;
                if (C8) {
                    *(unsigned short*)(C8 + base) = pack_e4m3x2(v0, v1);
                } else {
                    *(unsigned*)(Cb + base) = pack2(v0, v1);
                }
            }
            if (do_exp) {
                part += __shfl_xor_sync(0xffffffffu, part, 1);
                part += __shfl_xor_sync(0xffffffffu, part, 2);
                if ((lane & 3) == 0)
                    atomicAdd(rowsum + grow, part);
            }
        }
    }
}

// ---------------- launch -----------------------------------------------------
extern "C" void kernel_launch(void* const* d_in, const int* in_sizes, int n_in,
                              void* d_out, int out_size)
{
    const float* x     = (const float*)d_in[0];
    const float* gamma = (const float*)d_in[1];
    const float* beta  = (const float*)d_in[2];
    const float* wq    = (const float*)d_in[3];
    const float* bq    = (const float*)d_in[4];
    const float* wk    = (const float*)d_in[5];
    const float* bk    = (const float*)d_in[6];
    const float* wv    = (const float*)d_in[7];
    const float* bv    = (const float*)d_in[8];
    const float* wo    = (const float*)d_in[9];
    const float* bo    = (const float*)d_in[10];
    float* out = (float*)d_out;

    bf16 *xn, *ao, *wT;
    unsigned char *qk8, *vt8, *p8;
    float *rowsum, *bqk;
    cudaGetSymbolAddress((void**)&xn,  g_xn);
    cudaGetSymbolAddress((void**)&qk8, g_qk8);
    cudaGetSymbolAddress((void**)&vt8, g_vt8);
    cudaGetSymbolAddress((void**)&p8,  g_p8);
    cudaGetSymbolAddress((void**)&ao,  g_ao);
    cudaGetSymbolAddress((void**)&wT,  g_wT);
    cudaGetSymbolAddress((void**)&rowsum, g_rowsum);
    cudaGetSymbolAddress((void**)&bqk, g_bqk);

    static cudaStream_t s1 = nullptr;
    static cudaEvent_t eRoot = nullptr, eGN = nullptr, eAux = nullptr,
                       eQK = nullptr, eVT = nullptr, eS1 = nullptr;
    if (!s1) {
        cudaStreamCreateWithFlags(&s1, cudaStreamNonBlocking);
        cudaEventCreateWithFlags(&eRoot, cudaEventDisableTiming);
        cudaEventCreateWithFlags(&eGN,  cudaEventDisableTiming);
        cudaEventCreateWithFlags(&eAux, cudaEventDisableTiming);
        cudaEventCreateWithFlags(&eQK,  cudaEventDisableTiming);
        cudaEventCreateWithFlags(&eVT,  cudaEventDisableTiming);
        cudaEventCreateWithFlags(&eS1,  cudaEventDisableTiming);
    }

    const int SMEM_DYN = 2 * STAGE_BYTES;   // 64 KB
    cudaFuncSetAttribute(gemm_bf16, cudaFuncAttributeMaxDynamicSharedMemorySize,
                         SMEM_DYN);
    cudaFuncSetAttribute(gemm_fp8, cudaFuncAttributeMaxDynamicSharedMemorySize,
                         SMEM_DYN);

    const float scale = 0.044194173824159216f;   // 512^-0.5
    const long long HC  = (long long)HW_ * C_;
    const long long HH  = (long long)HW_ * HW_;
    const long long H2C = (long long)HW_ * 2 * C_;

    // ---- fork: root s1 in the capture graph BEFORE any s1 work ----
    cudaEventRecord(eRoot, 0);
    cudaStreamWaitEvent(s1, eRoot, 0);

    // ---- stage 0: GN (s0)  ||  wtrans + setup (s1) ----
    groupnorm_kernel<<<B_ * G_, 256>>>(x, gamma, beta, xn);
    cudaEventRecord(eGN, 0);
    wtrans_kernel<<<dim3(C_/32, C_/32, 4), 256, 0, s1>>>(wq, wk, wv, wo, wT);
    setup_kernel<<<MTOT/256, 256, 0, s1>>>(bq, bk, bqk, rowsum);
    cudaEventRecord(eAux, s1);
    cudaStreamWaitEvent(s1, eGN, 0);
    cudaStreamWaitEvent(0,  eAux, 0);

    // ---- stage 1: QK proj -> fp8 (s0)  ||  V^T proj -> fp8 (s1) ----
    gemm_bf16<<<dim3(2*C_/128, MTOT/128, 1), 256, SMEM_DYN>>>(
        xn, wT, MTOT, 2*C_, C_, C_, C_, 2*C_, 0, 0, 0,
        1.f, bqk, nullptr, nullptr, nullptr, nullptr, qk8);
    cudaEventRecord(eQK, 0);

    gemm_bf16<<<dim3(HW_/128, C_/128, B_), 256, SMEM_DYN, s1>>>(
        wT + 2*(size_t)C_*C_, xn, C_, HW_, C_, C_, C_, HW_,
        0, HC, (long long)C_*HW_,
        1.f, nullptr, bv, nullptr, nullptr, nullptr, vt8);
    cudaEventRecord(eVT, s1);
    cudaStreamWaitEvent(s1, eQK, 0);
    cudaStreamWaitEvent(0,  eVT, 0);

    // ---- stage 2: per-batch fp8 attention, pipelined on two streams ----
    // s0: b=0,2   s1: b=1,3
    for (int i = 0; i < 2; i++) {
        int b0 = 2 * i, b1 = 2 * i + 1;
        // exp-scores(b) = exp(scale * Q_b K_b^T) -> fp8, accumulate rowsum
        gemm_fp8<<<dim3(HW_/128, HW_/128, 1), 256, SMEM_DYN>>>(
            qk8 + (size_t)b0 * H2C, qk8 + (size_t)b0 * H2C + C_,
            HW_, HW_, C_, 2*C_, 2*C_, HW_,
            scale, p8 + (size_t)b0 * HH, nullptr,
            1, rowsum + (size_t)b0 * HW_, nullptr);
        gemm_fp8<<<dim3(HW_/128, HW_/128, 1), 256, SMEM_DYN, s1>>>(
            qk8 + (size_t)b1 * H2C, qk8 + (size_t)b1 * H2C + C_,
            HW_, HW_, C_, 2*C_, 2*C_, HW_,
            scale, p8 + (size_t)b1 * HH, nullptr,
            1, rowsum + (size_t)b1 * HW_, nullptr);
        // PV(b) = (P @ V) / rowsum -> bf16
        gemm_fp8<<<dim3(C_/128, HW_/128, 1), 256, SMEM_DYN>>>(
            p8 + (size_t)b0 * HH, vt8 + (size_t)b0 * C_ * HW_,
            HW_, C_, HW_, HW_, HW_, C_,
            1.f, nullptr, ao + (size_t)b0 * HC,
            0, nullptr, rowsum + (size_t)b0 * HW_);
        gemm_fp8<<<dim3(C_/128, HW_/128, 1), 256, SMEM_DYN, s1>>>(
            p8 + (size_t)b1 * HH, vt8 + (size_t)b1 * C_ * HW_,
            HW_, C_, HW_, HW_, HW_, C_,
            1.f, nullptr, ao + (size_t)b1 * HC,
            0, nullptr, rowsum + (size_t)b1 * HW_);
    }
    cudaEventRecord(eS1, s1);
    cudaStreamWaitEvent(0, eS1, 0);    // join

    // ---- stage 3: out = attn_out @ wo + bo + x -> fp32 ----
    gemm_bf16<<<dim3(C_/128, MTOT/128, 1), 256, SMEM_DYN>>>(
        ao, wT + 3*(size_t)C_*C_, MTOT, C_, C_, C_, C_, C_, 0, 0, 0,
        1.f, bo, nullptr, x, out, nullptr, nullptr);
}

// round 16
// speedup vs baseline: 1.1408x; 1.1408x over previous
#include <cuda_runtime.h>
#include <cuda_bf16.h>
#include <math.h>

#define B_   4
#define HW_  4096          // 64*64
#define C_   512
#define G_   32
#define CG_  16
#define MTOT (B_*HW_)      // 16384

typedef __nv_bfloat16 bf16;

// ---------------- scratch (device globals; no allocations allowed) ----------
__device__ bf16  g_xn[(size_t)MTOT*C_];
__device__ bf16  g_qk[(size_t)MTOT*2*C_];        // fused Q|K [16384][1024]
__device__ bf16  g_vt[(size_t)B_*C_*HW_];        // V^T per batch [512][4096]
__device__ bf16  g_s [(size_t)B_*HW_*HW_];       // bf16 exp-scores 128 MiB
__device__ bf16  g_ao[(size_t)MTOT*C_];
__device__ bf16  g_wT[(size_t)4*C_*C_];          // q,k,v,o transposed bf16
__device__ float g_rowsum[(size_t)MTOT];         // softmax denominators
__device__ float g_bqk[2*C_];                    // bq || bk

// ======================= helpers =============================================
__device__ __forceinline__ unsigned smem_u32(const void* p) {
    unsigned a;
    asm("{ .reg .u64 t; cvta.to.shared.u64 t, %1; cvt.u32.u64 %0, t; }"
        : "=r"(a) : "l"(p));
    return a;
}
__device__ __forceinline__ unsigned pack2(float a, float b) {
    __nv_bfloat162 t = __floats2bfloat162_rn(a, b);
    return *reinterpret_cast<unsigned*>(&t);
}

#define LDMX4(r, addr) \
    asm volatile("ldmatrix.sync.aligned.m8n8.x4.shared.b16 {%0,%1,%2,%3}, [%4];" \
        : "=r"((r)[0]), "=r"((r)[1]), "=r"((r)[2]), "=r"((r)[3]) : "r"(addr))

#define MMA16816(c, a, b0, b1) \
    asm volatile("mma.sync.aligned.m16n8k16.row.col.f32.bf16.bf16.f32 " \
        "{%0,%1,%2,%3}, {%4,%5,%6,%7}, {%8,%9}, {%0,%1,%2,%3};" \
        : "+f"((c)[0]), "+f"((c)[1]), "+f"((c)[2]), "+f"((c)[3]) \
        : "r"((a)[0]), "r"((a)[1]), "r"((a)[2]), "r"((a)[3]), "r"(b0), "r"(b1))

// ---------------- GroupNorm -> bf16 ----------------------------------------
__global__ __launch_bounds__(256) void groupnorm_kernel(
    const float* __restrict__ x, const float* __restrict__ gamma,
    const float* __restrict__ beta, bf16* __restrict__ xn)
{
    int bg = blockIdx.x;
    int b = bg / G_, g = bg % G_;
    const float* xp = x + (size_t)b * HW_ * C_ + g * CG_;
    bf16* op = xn + (size_t)b * HW_ * C_ + g * CG_;
    int tid = threadIdx.x;

    float s = 0.f, ss = 0.f;
    for (int p = tid; p < HW_; p += 256) {
        const float4* v4 = (const float4*)(xp + (size_t)p * C_);
        #pragma unroll
        for (int i = 0; i < 4; i++) {
            float4 t = v4[i];
            s  += t.x + t.y + t.z + t.w;
            ss += t.x*t.x + t.y*t.y + t.z*t.z + t.w*t.w;
        }
    }
    __shared__ float rs[256], rq[256];
    rs[tid] = s; rq[tid] = ss; __syncthreads();
    for (int o = 128; o > 0; o >>= 1) {
        if (tid < o) { rs[tid] += rs[tid+o]; rq[tid] += rq[tid+o]; }
        __syncthreads();
    }
    const float invn = 1.0f / (HW_ * CG_);
    float mean = rs[0] * invn;
    float var  = rq[0] * invn - mean * mean;
    float rstd = rsqrtf(var + 1e-6f);

    float gm[CG_], bt[CG_];
    #pragma unroll
    for (int i = 0; i < CG_; i++) {
        gm[i] = gamma[g*CG_ + i];
        bt[i] = beta [g*CG_ + i];
    }

    for (int p = tid; p < HW_; p += 256) {
        const float4* v4 = (const float4*)(xp + (size_t)p * C_);
        uint2* o2 = (uint2*)(op + (size_t)p * C_);
        #pragma unroll
        for (int i = 0; i < 4; i++) {
            float4 t = v4[i];
            float a0 = (t.x - mean) * rstd * gm[i*4+0] + bt[i*4+0];
            float a1 = (t.y - mean) * rstd * gm[i*4+1] + bt[i*4+1];
            float a2 = (t.z - mean) * rstd * gm[i*4+2] + bt[i*4+2];
            float a3 = (t.w - mean) * rstd * gm[i*4+3] + bt[i*4+3];
            uint2 u; u.x = pack2(a0, a1); u.y = pack2(a2, a3);
            o2[i] = u;
        }
    }
}

// ---------------- weight transpose+convert ----------------------------------
__global__ __launch_bounds__(256) void wtrans_kernel(
    const float* __restrict__ w0, const float* __restrict__ w1,
    const float* __restrict__ w2, const float* __restrict__ w3,
    bf16* __restrict__ out)
{
    int z = blockIdx.z;
    const float* w = (z == 0) ? w0 : (z == 1) ? w1 : (z == 2) ? w2 : w3;
    bf16* o = out + (size_t)z * C_ * C_;
    __shared__ float t[32][33];
    int c0 = blockIdx.x * 32, d0 = blockIdx.y * 32;
    int tx = threadIdx.x & 31, ty = threadIdx.x >> 5;
    #pragma unroll
    for (int i = 0; i < 32; i += 8)
        t[ty+i][tx] = w[(size_t)(c0+ty+i) * C_ + d0 + tx];
    __syncthreads();
    #pragma unroll
    for (int i = 0; i < 32; i += 8)
        o[(size_t)(d0+ty+i) * C_ + c0 + tx] = __float2bfloat16(t[tx][ty+i]);
}

// ---------------- tiny setup kernel -----------------------------------------
__global__ void setup_kernel(const float* __restrict__ bq,
                             const float* __restrict__ bk,
                             float* __restrict__ bqk,
                             float* __restrict__ rowsum)
{
    int i = blockIdx.x * 256 + threadIdx.x;
    if (i < 2*C_) bqk[i] = (i < C_) ? bq[i] : bk[i - C_];
    if (i < MTOT) rowsum[i] = 0.f;
}

// ---------------- HMMA bf16 GEMM: C = alpha*A@B^T + epilogue variants -------
// Block tile 128x128x64, 8 warps (2x4), warp tile 64x32, 2-stage cp.async.
// 128 regs, 64KB smem -> 2 CTAs/SM (co-residency across concurrent kernels).
#define KT 64
#define STAGE_BYTES 32768   // A 16KB + B 16KB

__device__ __forceinline__ void load_stage(
    unsigned base, const bf16* __restrict__ A, const bf16* __restrict__ B,
    int lda, int ldb, int brow, int bcol, int k0, int tid)
{
    #pragma unroll
    for (int i = 0; i < 4; i++) {
        int id  = i * 256 + tid;
        int row = id >> 3, cg = id & 7;
        const bf16* ga = A + (long long)(brow + row) * lda + k0 + cg * 8;
        unsigned sa = base + row * 128 + ((cg ^ (row & 7)) << 4);
        asm volatile("cp.async.cg.shared.global [%0], [%1], 16;" :: "r"(sa), "l"(ga));
        const bf16* gb = B + (long long)(bcol + row) * ldb + k0 + cg * 8;
        unsigned sb = base + 16384 + row * 128 + ((cg ^ (row & 7)) << 4);
        asm volatile("cp.async.cg.shared.global [%0], [%1], 16;" :: "r"(sb), "l"(gb));
    }
}

__global__ void __launch_bounds__(256, 2) gemm_bf16(
    const bf16* __restrict__ A, const bf16* __restrict__ B,
    int M, int N, int K, int lda, int ldb, int ldc,
    long long sA, long long sB, long long sC,
    float alpha,
    const float* __restrict__ cbias,
    const float* __restrict__ rbias,
    const float* __restrict__ resid,
    float* __restrict__ Cf, bf16* __restrict__ Cb,
    int do_exp, float* __restrict__ rowsum,
    const float* __restrict__ rdiv)
{
    extern __shared__ char smem[];
    const unsigned s0 = smem_u32(smem);
    const int tid = threadIdx.x, wid = tid >> 5, lane = tid & 31;
    const int warp_m = wid & 1, warp_n = wid >> 1;    // 2 x 4 warp grid

    A += (long long)blockIdx.z * sA;
    B += (long long)blockIdx.z * sB;
    const long long cb0 = (long long)blockIdx.z * sC;
    const int brow = blockIdx.y * 128, bcol = blockIdx.x * 128;
    const int rsbase = blockIdx.z * M;

    const int g  = lane >> 3, li = lane & 7;
    const int rowA = (g & 1) * 8 + li;
    const int kselA = g >> 1;
    const int rowB = (g >> 1) * 8 + li;
    const int kselB = g & 1;

    float acc[4][4][4];
    #pragma unroll
    for (int mt = 0; mt < 4; mt++)
        #pragma unroll
        for (int nt = 0; nt < 4; nt++)
            #pragma unroll
            for (int e = 0; e < 4; e++) acc[mt][nt][e] = 0.f;

    const int nc = K / KT;

    load_stage(s0, A, B, lda, ldb, brow, bcol, 0, tid);
    asm volatile("cp.async.commit_group;");

    for (int t = 0; t < nc; t++) {
        if (t + 1 < nc) {
            load_stage(s0 + ((t + 1) & 1) * STAGE_BYTES, A, B, lda, ldb,
                       brow, bcol, (t + 1) * KT, tid);
            asm volatile("cp.async.commit_group;");
            asm volatile("cp.async.wait_group 1;");
        } else {
            asm volatile("cp.async.wait_group 0;");
        }
        __syncthreads();

        const unsigned aBase = s0 + (t & 1) * STAGE_BYTES;
        const unsigned bBase = aBase + 16384;
        #pragma unroll
        for (int kk = 0; kk < 4; kk++) {
            unsigned af[4][4];
            #pragma unroll
            for (int mt = 0; mt < 4; mt++) {
                int r = warp_m * 64 + mt * 16 + rowA;
                unsigned addr = aBase + r * 128 + (((kk * 2 + kselA) ^ li) << 4);
                LDMX4(af[mt], addr);
            }
            unsigned bfx[2][4];
            #pragma unroll
            for (int nh = 0; nh < 2; nh++) {
                int r = warp_n * 32 + nh * 16 + rowB;
                unsigned addr = bBase + r * 128 + (((kk * 2 + kselB) ^ li) << 4);
                LDMX4(bfx[nh], addr);
            }
            #pragma unroll
            for (int mt = 0; mt < 4; mt++) {
                #pragma unroll
                for (int nt = 0; nt < 4; nt++) {
                    unsigned b0 = bfx[nt >> 1][(nt & 1) * 2];
                    unsigned b1 = bfx[nt >> 1][(nt & 1) * 2 + 1];
                    MMA16816(acc[mt][nt], af[mt], b0, b1);
                }
            }
        }
        __syncthreads();
    }

    // epilogue
    const int er = lane >> 2, ec = (lane & 3) * 2;
    #pragma unroll
    for (int mt = 0; mt < 4; mt++) {
        #pragma unroll
        for (int half = 0; half < 2; half++) {
            long long grow = brow + warp_m * 64 + mt * 16 + er + half * 8;
            float rb = rbias ? rbias[grow] : 0.f;
            float rsc = rdiv ? (1.0f / rdiv[rsbase + grow]) : 1.0f;
            float part = 0.f;
            #pragma unroll
            for (int nt = 0; nt < 4; nt++) {
                int col = bcol + warp_n * 32 + nt * 8 + ec;
                float v0 = acc[mt][nt][half * 2]     * alpha + rb;
                float v1 = acc[mt][nt][half * 2 + 1] * alpha + rb;
                if (cbias) { v0 += cbias[col]; v1 += cbias[col + 1]; }
                if (do_exp) { v0 = __expf(v0); v1 = __expf(v1); part += v0 + v1; }
                v0 *= rsc; v1 *= rsc;
                long long base = cb0 + grow * (long long)ldc + col;
                if (resid) {
                    float2 r = *(const float2*)(resid + base);
                    v0 += r.x; v1 += r.y;
                }
                if (Cf) {
                    float2 o = {v0, v1};
                    *(float2*)(Cf + base) = o;
                } else {
                    *(unsigned*)(Cb + base) = pack2(v0, v1);
                }
            }
            if (do_exp) {
                part += __shfl_xor_sync(0xffffffffu, part, 1);
                part += __shfl_xor_sync(0xffffffffu, part, 2);
                if ((lane & 3) == 0)
                    atomicAdd(rowsum + rsbase + grow, part);
            }
        }
    }
}

// ---------------- launch -----------------------------------------------------
extern "C" void kernel_launch(void* const* d_in, const int* in_sizes, int n_in,
                              void* d_out, int out_size)
{
    const float* x     = (const float*)d_in[0];
    const float* gamma = (const float*)d_in[1];
    const float* beta  = (const float*)d_in[2];
    const float* wq    = (const float*)d_in[3];
    const float* bq    = (const float*)d_in[4];
    const float* wk    = (const float*)d_in[5];
    const float* bk    = (const float*)d_in[6];
    const float* wv    = (const float*)d_in[7];
    const float* bv    = (const float*)d_in[8];
    const float* wo    = (const float*)d_in[9];
    const float* bo    = (const float*)d_in[10];
    float* out = (float*)d_out;

    bf16 *xn, *qk, *vt, *s, *ao, *wT;
    float *rowsum, *bqk;
    cudaGetSymbolAddress((void**)&xn, g_xn);
    cudaGetSymbolAddress((void**)&qk, g_qk);
    cudaGetSymbolAddress((void**)&vt, g_vt);
    cudaGetSymbolAddress((void**)&s,  g_s);
    cudaGetSymbolAddress((void**)&ao, g_ao);
    cudaGetSymbolAddress((void**)&wT, g_wT);
    cudaGetSymbolAddress((void**)&rowsum, g_rowsum);
    cudaGetSymbolAddress((void**)&bqk, g_bqk);

    // one-time resources (no device memory): 3 side streams + fork/join events
    static cudaStream_t st[4] = {nullptr, nullptr, nullptr, nullptr};  // st[0]=legacy
    static cudaEvent_t eRoot = nullptr, eGN = nullptr, eAux = nullptr,
                       eQK = nullptr, eVT = nullptr;
    static cudaEvent_t eDone[4] = {nullptr, nullptr, nullptr, nullptr};
    if (!st[1]) {
        st[0] = nullptr;  // default stream
        cudaStreamCreateWithFlags(&st[1], cudaStreamNonBlocking);
        cudaStreamCreateWithFlags(&st[2], cudaStreamNonBlocking);
        cudaStreamCreateWithFlags(&st[3], cudaStreamNonBlocking);
        cudaEventCreateWithFlags(&eRoot, cudaEventDisableTiming);
        cudaEventCreateWithFlags(&eGN,  cudaEventDisableTiming);
        cudaEventCreateWithFlags(&eAux, cudaEventDisableTiming);
        cudaEventCreateWithFlags(&eQK,  cudaEventDisableTiming);
        cudaEventCreateWithFlags(&eVT,  cudaEventDisableTiming);
        for (int i = 0; i < 4; i++)
            cudaEventCreateWithFlags(&eDone[i], cudaEventDisableTiming);
    }

    const int SMEM_DYN = 2 * STAGE_BYTES;   // 64 KB
    cudaFuncSetAttribute(gemm_bf16, cudaFuncAttributeMaxDynamicSharedMemorySize,
                         SMEM_DYN);

    const float scale = 0.044194173824159216f;   // 512^-0.5
    const long long HC  = (long long)HW_ * C_;
    const long long HH  = (long long)HW_ * HW_;
    const long long H2C = (long long)HW_ * 2 * C_;

    // ---- fork: root side streams in the capture graph before their first use
    cudaEventRecord(eRoot, 0);
    cudaStreamWaitEvent(st[1], eRoot, 0);
    cudaStreamWaitEvent(st[2], eRoot, 0);
    cudaStreamWaitEvent(st[3], eRoot, 0);

    // ---- stage 0: GN (s0)  ||  wtrans + setup (st1) ----
    groupnorm_kernel<<<B_ * G_, 256>>>(x, gamma, beta, xn);
    cudaEventRecord(eGN, 0);
    wtrans_kernel<<<dim3(C_/32, C_/32, 4), 256, 0, st[1]>>>(wq, wk, wv, wo, wT);
    setup_kernel<<<MTOT/256, 256, 0, st[1]>>>(bq, bk, bqk, rowsum);
    cudaEventRecord(eAux, st[1]);
    cudaStreamWaitEvent(st[1], eGN, 0);   // st1 now has: weights + xn
    cudaStreamWaitEvent(0,     eAux, 0);  // s0 now has: bqk + rowsum zeroed

    // ---- stage 1: QK proj (s0)  ||  V^T proj (st1) ----
    gemm_bf16<<<dim3(2*C_/128, MTOT/128, 1), 256, SMEM_DYN>>>(
        xn, wT, MTOT, 2*C_, C_, C_, C_, 2*C_, 0, 0, 0,
        1.f, bqk, nullptr, nullptr, nullptr, qk, 0, nullptr, nullptr);
    cudaEventRecord(eQK, 0);

    gemm_bf16<<<dim3(HW_/128, C_/128, B_), 256, SMEM_DYN, st[1]>>>(
        wT + 2*(size_t)C_*C_, xn, C_, HW_, C_, C_, C_, HW_,
        0, HC, (long long)C_*HW_,
        1.f, nullptr, bv, nullptr, nullptr, vt, 0, nullptr, nullptr);
    cudaEventRecord(eVT, st[1]);

    // all four attention streams need Q,K (eQK) and V^T (eVT)
    cudaStreamWaitEvent(0,     eVT, 0);
    cudaStreamWaitEvent(st[1], eQK, 0);
    cudaStreamWaitEvent(st[2], eQK, 0);
    cudaStreamWaitEvent(st[2], eVT, 0);
    cudaStreamWaitEvent(st[3], eQK, 0);
    cudaStreamWaitEvent(st[3], eVT, 0);

    // ---- stage 2: per-batch attention chains, one stream each ----
    for (int b = 0; b < B_; b++) {
        cudaStream_t sb = st[b];  // st[0]==nullptr -> default stream
        // exp-scores(b) = exp(scale * Q_b K_b^T) -> bf16, accumulate rowsum
        gemm_bf16<<<dim3(HW_/128, HW_/128, 1), 256, SMEM_DYN, sb>>>(
            qk + (size_t)b * H2C, qk + (size_t)b * H2C + C_,
            HW_, HW_, C_, 2*C_, 2*C_, HW_, 0, 0, 0,
            scale, nullptr, nullptr, nullptr, nullptr, s + (size_t)b * HH,
            1, rowsum + (size_t)b * HW_, nullptr);
        // PV(b) = (P_unnorm @ V) / rowsum -> bf16
        gemm_bf16<<<dim3(C_/128, HW_/128, 1), 256, SMEM_DYN, sb>>>(
            s + (size_t)b * HH, vt + (size_t)b * C_ * HW_,
            HW_, C_, HW_, HW_, HW_, C_, 0, 0, 0,
            1.f, nullptr, nullptr, nullptr, nullptr, ao + (size_t)b * HC,
            0, nullptr, rowsum + (size_t)b * HW_);
        // out(b) = attn_out(b) @ wo + bo + x(b) -> fp32
        gemm_bf16<<<dim3(C_/128, HW_/128, 1), 256, SMEM_DYN, sb>>>(
            ao + (size_t)b * HC, wT + 3*(size_t)C_*C_,
            HW_, C_, C_, C_, C_, C_, 0, 0, 0,
            1.f, bo, nullptr, x + (size_t)b * HC,
            out + (size_t)b * HC, nullptr, 0, nullptr, nullptr);
        if (b > 0) cudaEventRecord(eDone[b], sb);
    }
    // join all side streams into stream 0
    cudaStreamWaitEvent(0, eDone[1], 0);
    cudaStreamWaitEvent(0, eDone[2], 0);
    cudaStreamWaitEvent(0, eDone[3], 0);
}

// round 17
// speedup vs baseline: 1.2001x; 1.0520x over previous
#include <cuda_runtime.h>
#include <cuda_fp16.h>
#include <math.h>

#define B_   4
#define HW_  4096          // 64*64
#define C_   512
#define G_   32
#define CG_  16
#define MTOT (B_*HW_)      // 16384

typedef __half hf;

// ---------------- scratch (device globals; no allocations allowed) ----------
__device__ hf    g_xn[(size_t)MTOT*C_];
__device__ hf    g_qk[(size_t)MTOT*2*C_];        // fused Q|K [16384][1024]
__device__ hf    g_vt[(size_t)B_*C_*HW_];        // V^T per batch [512][4096]
__device__ hf    g_s [(size_t)B_*HW_*HW_];       // fp16 exp-scores 128 MiB
__device__ hf    g_ao[(size_t)MTOT*C_];
__device__ hf    g_wT[(size_t)4*C_*C_];          // q,k,v,o transposed fp16
__device__ float g_rowsum[(size_t)MTOT];         // softmax denominators
__device__ float g_bqk[2*C_];                    // bq || bk

// ======================= helpers =============================================
__device__ __forceinline__ unsigned smem_u32(const void* p) {
    unsigned a;
    asm("{ .reg .u64 t; cvta.to.shared.u64 t, %1; cvt.u32.u64 %0, t; }"
        : "=r"(a) : "l"(p));
    return a;
}
__device__ __forceinline__ unsigned pack2(float a, float b) {
    __half2 t = __floats2half2_rn(a, b);
    return *reinterpret_cast<unsigned*>(&t);
}

#define LDMX4(r, addr) \
    asm volatile("ldmatrix.sync.aligned.m8n8.x4.shared.b16 {%0,%1,%2,%3}, [%4];" \
        : "=r"((r)[0]), "=r"((r)[1]), "=r"((r)[2]), "=r"((r)[3]) : "r"(addr))

// fp16 inputs, fp32 accumulate
#define MMA16816(c, a, b0, b1) \
    asm volatile("mma.sync.aligned.m16n8k16.row.col.f32.f16.f16.f32 " \
        "{%0,%1,%2,%3}, {%4,%5,%6,%7}, {%8,%9}, {%0,%1,%2,%3};" \
        : "+f"((c)[0]), "+f"((c)[1]), "+f"((c)[2]), "+f"((c)[3]) \
        : "r"((a)[0]), "r"((a)[1]), "r"((a)[2]), "r"((a)[3]), "r"(b0), "r"(b1))

// fp16 inputs, fp16 accumulate (2 b32 regs = 4 halves)
#define MMA16816H(c, a, b0, b1) \
    asm volatile("mma.sync.aligned.m16n8k16.row.col.f16.f16.f16.f16 " \
        "{%0,%1}, {%2,%3,%4,%5}, {%6,%7}, {%0,%1};" \
        : "+r"((c)[0]), "+r"((c)[1]) \
        : "r"((a)[0]), "r"((a)[1]), "r"((a)[2]), "r"((a)[3]), "r"(b0), "r"(b1))

// ---------------- GroupNorm -> fp16 -----------------------------------------
__global__ __launch_bounds__(256) void groupnorm_kernel(
    const float* __restrict__ x, const float* __restrict__ gamma,
    const float* __restrict__ beta, hf* __restrict__ xn)
{
    int bg = blockIdx.x;
    int b = bg / G_, g = bg % G_;
    const float* xp = x + (size_t)b * HW_ * C_ + g * CG_;
    hf* op = xn + (size_t)b * HW_ * C_ + g * CG_;
    int tid = threadIdx.x;

    float s = 0.f, ss = 0.f;
    for (int p = tid; p < HW_; p += 256) {
        const float4* v4 = (const float4*)(xp + (size_t)p * C_);
        #pragma unroll
        for (int i = 0; i < 4; i++) {
            float4 t = v4[i];
            s  += t.x + t.y + t.z + t.w;
            ss += t.x*t.x + t.y*t.y + t.z*t.z + t.w*t.w;
        }
    }
    __shared__ float rs[256], rq[256];
    rs[tid] = s; rq[tid] = ss; __syncthreads();
    for (int o = 128; o > 0; o >>= 1) {
        if (tid < o) { rs[tid] += rs[tid+o]; rq[tid] += rq[tid+o]; }
        __syncthreads();
    }
    const float invn = 1.0f / (HW_ * CG_);
    float mean = rs[0] * invn;
    float var  = rq[0] * invn - mean * mean;
    float rstd = rsqrtf(var + 1e-6f);

    float gm[CG_], bt[CG_];
    #pragma unroll
    for (int i = 0; i < CG_; i++) {
        gm[i] = gamma[g*CG_ + i];
        bt[i] = beta [g*CG_ + i];
    }

    for (int p = tid; p < HW_; p += 256) {
        const float4* v4 = (const float4*)(xp + (size_t)p * C_);
        uint2* o2 = (uint2*)(op + (size_t)p * C_);
        #pragma unroll
        for (int i = 0; i < 4; i++) {
            float4 t = v4[i];
            float a0 = (t.x - mean) * rstd * gm[i*4+0] + bt[i*4+0];
            float a1 = (t.y - mean) * rstd * gm[i*4+1] + bt[i*4+1];
            float a2 = (t.z - mean) * rstd * gm[i*4+2] + bt[i*4+2];
            float a3 = (t.w - mean) * rstd * gm[i*4+3] + bt[i*4+3];
            uint2 u; u.x = pack2(a0, a1); u.y = pack2(a2, a3);
            o2[i] = u;
        }
    }
}

// ---------------- weight transpose+convert ----------------------------------
__global__ __launch_bounds__(256) void wtrans_kernel(
    const float* __restrict__ w0, const float* __restrict__ w1,
    const float* __restrict__ w2, const float* __restrict__ w3,
    hf* __restrict__ out)
{
    int z = blockIdx.z;
    const float* w = (z == 0) ? w0 : (z == 1) ? w1 : (z == 2) ? w2 : w3;
    hf* o = out + (size_t)z * C_ * C_;
    __shared__ float t[32][33];
    int c0 = blockIdx.x * 32, d0 = blockIdx.y * 32;
    int tx = threadIdx.x & 31, ty = threadIdx.x >> 5;
    #pragma unroll
    for (int i = 0; i < 32; i += 8)
        t[ty+i][tx] = w[(size_t)(c0+ty+i) * C_ + d0 + tx];
    __syncthreads();
    #pragma unroll
    for (int i = 0; i < 32; i += 8)
        o[(size_t)(d0+ty+i) * C_ + c0 + tx] = __float2half(t[tx][ty+i]);
}

// ---------------- tiny setup kernel -----------------------------------------
__global__ void setup_kernel(const float* __restrict__ bq,
                             const float* __restrict__ bk,
                             float* __restrict__ bqk,
                             float* __restrict__ rowsum)
{
    int i = blockIdx.x * 256 + threadIdx.x;
    if (i < 2*C_) bqk[i] = (i < C_) ? bq[i] : bk[i - C_];
    if (i < MTOT) rowsum[i] = 0.f;
}

// ---------------- generic fp16 GEMM (f32 accum): C = alpha*A@B^T + epilogues
// Block tile 128x128x64, 8 warps (2x4), warp tile 64x32, 2-stage cp.async.
#define KT 64
#define STAGE_BYTES 32768   // A 16KB + B 16KB

__device__ __forceinline__ void load_stage(
    unsigned base, const hf* __restrict__ A, const hf* __restrict__ B,
    int lda, int ldb, int brow, int bcol, int k0, int tid)
{
    #pragma unroll
    for (int i = 0; i < 4; i++) {
        int id  = i * 256 + tid;
        int row = id >> 3, cg = id & 7;
        const hf* ga = A + (long long)(brow + row) * lda + k0 + cg * 8;
        unsigned sa = base + row * 128 + ((cg ^ (row & 7)) << 4);
        asm volatile("cp.async.cg.shared.global [%0], [%1], 16;" :: "r"(sa), "l"(ga));
        const hf* gb = B + (long long)(bcol + row) * ldb + k0 + cg * 8;
        unsigned sb = base + 16384 + row * 128 + ((cg ^ (row & 7)) << 4);
        asm volatile("cp.async.cg.shared.global [%0], [%1], 16;" :: "r"(sb), "l"(gb));
    }
}

__global__ void __launch_bounds__(256, 2) gemm_h(
    const hf* __restrict__ A, const hf* __restrict__ B,
    int M, int N, int K, int lda, int ldb, int ldc,
    long long sA, long long sB, long long sC,
    float alpha,
    const float* __restrict__ cbias,
    const float* __restrict__ rbias,
    const float* __restrict__ resid,
    float* __restrict__ Cf, hf* __restrict__ Cb,
    const float* __restrict__ rdiv)
{
    extern __shared__ char smem[];
    const unsigned s0 = smem_u32(smem);
    const int tid = threadIdx.x, wid = tid >> 5, lane = tid & 31;
    const int warp_m = wid & 1, warp_n = wid >> 1;

    A += (long long)blockIdx.z * sA;
    B += (long long)blockIdx.z * sB;
    const long long cb0 = (long long)blockIdx.z * sC;
    const int brow = blockIdx.y * 128, bcol = blockIdx.x * 128;
    const int rsbase = blockIdx.z * M;

    const int g  = lane >> 3, li = lane & 7;
    const int rowA = (g & 1) * 8 + li;
    const int kselA = g >> 1;
    const int rowB = (g >> 1) * 8 + li;
    const int kselB = g & 1;

    float acc[4][4][4];
    #pragma unroll
    for (int mt = 0; mt < 4; mt++)
        #pragma unroll
        for (int nt = 0; nt < 4; nt++)
            #pragma unroll
            for (int e = 0; e < 4; e++) acc[mt][nt][e] = 0.f;

    const int nc = K / KT;

    load_stage(s0, A, B, lda, ldb, brow, bcol, 0, tid);
    asm volatile("cp.async.commit_group;");

    for (int t = 0; t < nc; t++) {
        if (t + 1 < nc) {
            load_stage(s0 + ((t + 1) & 1) * STAGE_BYTES, A, B, lda, ldb,
                       brow, bcol, (t + 1) * KT, tid);
            asm volatile("cp.async.commit_group;");
            asm volatile("cp.async.wait_group 1;");
        } else {
            asm volatile("cp.async.wait_group 0;");
        }
        __syncthreads();

        const unsigned aBase = s0 + (t & 1) * STAGE_BYTES;
        const unsigned bBase = aBase + 16384;
        #pragma unroll
        for (int kk = 0; kk < 4; kk++) {
            unsigned af[4][4];
            #pragma unroll
            for (int mt = 0; mt < 4; mt++) {
                int r = warp_m * 64 + mt * 16 + rowA;
                unsigned addr = aBase + r * 128 + (((kk * 2 + kselA) ^ li) << 4);
                LDMX4(af[mt], addr);
            }
            unsigned bfx[2][4];
            #pragma unroll
            for (int nh = 0; nh < 2; nh++) {
                int r = warp_n * 32 + nh * 16 + rowB;
                unsigned addr = bBase + r * 128 + (((kk * 2 + kselB) ^ li) << 4);
                LDMX4(bfx[nh], addr);
            }
            #pragma unroll
            for (int mt = 0; mt < 4; mt++) {
                #pragma unroll
                for (int nt = 0; nt < 4; nt++) {
                    unsigned b0 = bfx[nt >> 1][(nt & 1) * 2];
                    unsigned b1 = bfx[nt >> 1][(nt & 1) * 2 + 1];
                    MMA16816(acc[mt][nt], af[mt], b0, b1);
                }
            }
        }
        __syncthreads();
    }

    const int er = lane >> 2, ec = (lane & 3) * 2;
    #pragma unroll
    for (int mt = 0; mt < 4; mt++) {
        #pragma unroll
        for (int half = 0; half < 2; half++) {
            long long grow = brow + warp_m * 64 + mt * 16 + er + half * 8;
            float rb = rbias ? rbias[grow] : 0.f;
            float rsc = rdiv ? (1.0f / rdiv[rsbase + grow]) : 1.0f;
            #pragma unroll
            for (int nt = 0; nt < 4; nt++) {
                int col = bcol + warp_n * 32 + nt * 8 + ec;
                float v0 = acc[mt][nt][half * 2]     * alpha + rb;
                float v1 = acc[mt][nt][half * 2 + 1] * alpha + rb;
                if (cbias) { v0 += cbias[col]; v1 += cbias[col + 1]; }
                v0 *= rsc; v1 *= rsc;
                long long base = cb0 + grow * (long long)ldc + col;
                if (resid) {
                    float2 r = *(const float2*)(resid + base);
                    v0 += r.x; v1 += r.y;
                }
                if (Cf) {
                    float2 o = {v0, v1};
                    *(float2*)(Cf + base) = o;
                } else {
                    *(unsigned*)(Cb + base) = pack2(v0, v1);
                }
            }
        }
    }
}

// ---------------- scores GEMM: f16 accum, warp tile 64x64, block 128x256 ----
// P = exp(alpha * Q@K^T) in fp16, accumulating fp32 rowsums.
#define STAGE_QK 49152   // A 16KB + B 32KB

__device__ __forceinline__ void load_stage_qk(
    unsigned base, const hf* __restrict__ A, const hf* __restrict__ B,
    int lda, int ldb, int brow, int bcol, int k0, int tid)
{
    #pragma unroll
    for (int i = 0; i < 4; i++) {
        int id  = i * 256 + tid;
        int row = id >> 3, cg = id & 7;
        const hf* ga = A + (long long)(brow + row) * lda + k0 + cg * 8;
        unsigned sa = base + row * 128 + ((cg ^ (row & 7)) << 4);
        asm volatile("cp.async.cg.shared.global [%0], [%1], 16;" :: "r"(sa), "l"(ga));
    }
    #pragma unroll
    for (int i = 0; i < 8; i++) {
        int id  = i * 256 + tid;
        int row = id >> 3, cg = id & 7;
        const hf* gb = B + (long long)(bcol + row) * ldb + k0 + cg * 8;
        unsigned sb = base + 16384 + row * 128 + ((cg ^ (row & 7)) << 4);
        asm volatile("cp.async.cg.shared.global [%0], [%1], 16;" :: "r"(sb), "l"(gb));
    }
}

__global__ void __launch_bounds__(256, 2) gemm_qk(
    const hf* __restrict__ A, const hf* __restrict__ B,
    int K, int lda, int ldb, int ldc,
    float alpha,
    hf* __restrict__ P, float* __restrict__ rowsum)
{
    extern __shared__ char smem[];
    const unsigned s0 = smem_u32(smem);
    const int tid = threadIdx.x, wid = tid >> 5, lane = tid & 31;
    const int warp_m = wid & 1, warp_n = wid >> 1;   // 2 x 4; warp tile 64x64

    const int brow = blockIdx.y * 128, bcol = blockIdx.x * 256;

    const int g  = lane >> 3, li = lane & 7;
    const int rowA = (g & 1) * 8 + li;
    const int kselA = g >> 1;
    const int rowB = (g >> 1) * 8 + li;
    const int kselB = g & 1;

    unsigned acc[4][8][2];   // f16x2 accumulators
    #pragma unroll
    for (int mt = 0; mt < 4; mt++)
        #pragma unroll
        for (int nt = 0; nt < 8; nt++) { acc[mt][nt][0] = 0u; acc[mt][nt][1] = 0u; }

    const int nc = K / KT;

    load_stage_qk(s0, A, B, lda, ldb, brow, bcol, 0, tid);
    asm volatile("cp.async.commit_group;");

    for (int t = 0; t < nc; t++) {
        if (t + 1 < nc) {
            load_stage_qk(s0 + ((t + 1) & 1) * STAGE_QK, A, B, lda, ldb,
                          brow, bcol, (t + 1) * KT, tid);
            asm volatile("cp.async.commit_group;");
            asm volatile("cp.async.wait_group 1;");
        } else {
            asm volatile("cp.async.wait_group 0;");
        }
        __syncthreads();

        const unsigned aBase = s0 + (t & 1) * STAGE_QK;
        const unsigned bBase = aBase + 16384;
        #pragma unroll
        for (int kk = 0; kk < 4; kk++) {
            unsigned af[4][4];
            #pragma unroll
            for (int mt = 0; mt < 4; mt++) {
                int r = warp_m * 64 + mt * 16 + rowA;
                unsigned addr = aBase + r * 128 + (((kk * 2 + kselA) ^ li) << 4);
                LDMX4(af[mt], addr);
            }
            unsigned bfx[4][4];
            #pragma unroll
            for (int nh = 0; nh < 4; nh++) {
                int r = warp_n * 64 + nh * 16 + rowB;
                unsigned addr = bBase + r * 128 + (((kk * 2 + kselB) ^ li) << 4);
                LDMX4(bfx[nh], addr);
            }
            #pragma unroll
            for (int mt = 0; mt < 4; mt++) {
                #pragma unroll
                for (int nt = 0; nt < 8; nt++) {
                    unsigned b0 = bfx[nt >> 1][(nt & 1) * 2];
                    unsigned b1 = bfx[nt >> 1][(nt & 1) * 2 + 1];
                    MMA16816H(acc[mt][nt], af[mt], b0, b1);
                }
            }
        }
        __syncthreads();
    }

    // epilogue: exp + rowsum + fp16 store
    const int er = lane >> 2, ec = (lane & 3) * 2;
    #pragma unroll
    for (int mt = 0; mt < 4; mt++) {
        #pragma unroll
        for (int half = 0; half < 2; half++) {
            long long grow = brow + warp_m * 64 + mt * 16 + er + half * 8;
            float part = 0.f;
            #pragma unroll
            for (int nt = 0; nt < 8; nt++) {
                int col = bcol + warp_n * 64 + nt * 8 + ec;
                float2 d = __half22float2(
                    *reinterpret_cast<__half2*>(&acc[mt][nt][half]));
                float v0 = __expf(d.x * alpha);
                float v1 = __expf(d.y * alpha);
                part += v0 + v1;
                long long base = grow * (long long)ldc + col;
                *(unsigned*)(P + base) = pack2(v0, v1);
            }
            part += __shfl_xor_sync(0xffffffffu, part, 1);
            part += __shfl_xor_sync(0xffffffffu, part, 2);
            if ((lane & 3) == 0)
                atomicAdd(rowsum + grow, part);
        }
    }
}

// ---------------- launch -----------------------------------------------------
extern "C" void kernel_launch(void* const* d_in, const int* in_sizes, int n_in,
                              void* d_out, int out_size)
{
    const float* x     = (const float*)d_in[0];
    const float* gamma = (const float*)d_in[1];
    const float* beta  = (const float*)d_in[2];
    const float* wq    = (const float*)d_in[3];
    const float* bq    = (const float*)d_in[4];
    const float* wk    = (const float*)d_in[5];
    const float* bk    = (const float*)d_in[6];
    const float* wv    = (const float*)d_in[7];
    const float* bv    = (const float*)d_in[8];
    const float* wo    = (const float*)d_in[9];
    const float* bo    = (const float*)d_in[10];
    float* out = (float*)d_out;

    hf *xn, *qk, *vt, *s, *ao, *wT;
    float *rowsum, *bqk;
    cudaGetSymbolAddress((void**)&xn, g_xn);
    cudaGetSymbolAddress((void**)&qk, g_qk);
    cudaGetSymbolAddress((void**)&vt, g_vt);
    cudaGetSymbolAddress((void**)&s,  g_s);
    cudaGetSymbolAddress((void**)&ao, g_ao);
    cudaGetSymbolAddress((void**)&wT, g_wT);
    cudaGetSymbolAddress((void**)&rowsum, g_rowsum);
    cudaGetSymbolAddress((void**)&bqk, g_bqk);

    static cudaStream_t st[4] = {nullptr, nullptr, nullptr, nullptr};
    static cudaEvent_t eRoot = nullptr, eGN = nullptr, eAux = nullptr,
                       eQK = nullptr, eVT = nullptr;
    static cudaEvent_t eDone[4] = {nullptr, nullptr, nullptr, nullptr};
    if (!st[1]) {
        st[0] = nullptr;  // default stream
        cudaStreamCreateWithFlags(&st[1], cudaStreamNonBlocking);
        cudaStreamCreateWithFlags(&st[2], cudaStreamNonBlocking);
        cudaStreamCreateWithFlags(&st[3], cudaStreamNonBlocking);
        cudaEventCreateWithFlags(&eRoot, cudaEventDisableTiming);
        cudaEventCreateWithFlags(&eGN,  cudaEventDisableTiming);
        cudaEventCreateWithFlags(&eAux, cudaEventDisableTiming);
        cudaEventCreateWithFlags(&eQK,  cudaEventDisableTiming);
        cudaEventCreateWithFlags(&eVT,  cudaEventDisableTiming);
        for (int i = 0; i < 4; i++)
            cudaEventCreateWithFlags(&eDone[i], cudaEventDisableTiming);
    }

    const int SMEM_DYN = 2 * STAGE_BYTES;   // 64 KB
    const int SMEM_QK  = 2 * STAGE_QK;      // 96 KB
    cudaFuncSetAttribute(gemm_h, cudaFuncAttributeMaxDynamicSharedMemorySize,
                         SMEM_DYN);
    cudaFuncSetAttribute(gemm_qk, cudaFuncAttributeMaxDynamicSharedMemorySize,
                         SMEM_QK);

    const float scale = 0.044194173824159216f;   // 512^-0.5
    const long long HC  = (long long)HW_ * C_;
    const long long HH  = (long long)HW_ * HW_;
    const long long H2C = (long long)HW_ * 2 * C_;

    // ---- fork roots ----
    cudaEventRecord(eRoot, 0);
    cudaStreamWaitEvent(st[1], eRoot, 0);
    cudaStreamWaitEvent(st[2], eRoot, 0);
    cudaStreamWaitEvent(st[3], eRoot, 0);

    // ---- stage 0: GN (s0)  ||  wtrans + setup (st1) ----
    groupnorm_kernel<<<B_ * G_, 256>>>(x, gamma, beta, xn);
    cudaEventRecord(eGN, 0);
    wtrans_kernel<<<dim3(C_/32, C_/32, 4), 256, 0, st[1]>>>(wq, wk, wv, wo, wT);
    setup_kernel<<<MTOT/256, 256, 0, st[1]>>>(bq, bk, bqk, rowsum);
    cudaEventRecord(eAux, st[1]);
    cudaStreamWaitEvent(st[1], eGN, 0);
    cudaStreamWaitEvent(0,     eAux, 0);

    // ---- stage 1: QK proj (s0)  ||  V^T proj (st1) ----
    gemm_h<<<dim3(2*C_/128, MTOT/128, 1), 256, SMEM_DYN>>>(
        xn, wT, MTOT, 2*C_, C_, C_, C_, 2*C_, 0, 0, 0,
        1.f, bqk, nullptr, nullptr, nullptr, qk, nullptr);
    cudaEventRecord(eQK, 0);

    gemm_h<<<dim3(HW_/128, C_/128, B_), 256, SMEM_DYN, st[1]>>>(
        wT + 2*(size_t)C_*C_, xn, C_, HW_, C_, C_, C_, HW_,
        0, HC, (long long)C_*HW_,
        1.f, nullptr, bv, nullptr, nullptr, vt, nullptr);
    cudaEventRecord(eVT, st[1]);

    cudaStreamWaitEvent(0,     eVT, 0);
    cudaStreamWaitEvent(st[1], eQK, 0);
    cudaStreamWaitEvent(st[2], eQK, 0);
    cudaStreamWaitEvent(st[2], eVT, 0);
    cudaStreamWaitEvent(st[3], eQK, 0);
    cudaStreamWaitEvent(st[3], eVT, 0);

    // ---- stage 2: per-batch attention chains, one stream each ----
    for (int b = 0; b < B_; b++) {
        cudaStream_t sb = st[b];
        // exp-scores(b): f16-accum 128x256-tile kernel
        gemm_qk<<<dim3(HW_/256, HW_/128, 1), 256, SMEM_QK, sb>>>(
            qk + (size_t)b * H2C, qk + (size_t)b * H2C + C_,
            C_, 2*C_, 2*C_, HW_,
            scale, s + (size_t)b * HH, rowsum + (size_t)b * HW_);
        // PV(b) = (P_unnorm @ V) / rowsum -> fp16
        gemm_h<<<dim3(C_/128, HW_/128, 1), 256, SMEM_DYN, sb>>>(
            s + (size_t)b * HH, vt + (size_t)b * C_ * HW_,
            HW_, C_, HW_, HW_, HW_, C_, 0, 0, 0,
            1.f, nullptr, nullptr, nullptr, nullptr, ao + (size_t)b * HC,
            rowsum + (size_t)b * HW_);
        // out(b) = attn_out(b) @ wo + bo + x(b) -> fp32
        gemm_h<<<dim3(C_/128, HW_/128, 1), 256, SMEM_DYN, sb>>>(
            ao + (size_t)b * HC, wT + 3*(size_t)C_*C_,
            HW_, C_, C_, C_, C_, C_, 0, 0, 0,
            1.f, bo, nullptr, x + (size_t)b * HC,
            out + (size_t)b * HC, nullptr, nullptr);
        if (b > 0) cudaEventRecord(eDone[b], sb);
    }
    cudaStreamWaitEvent(0, eDone[1], 0);
    cudaStreamWaitEvent(0, eDone[2], 0);
    cudaStreamWaitEvent(0, eDone[3], 0);
}